// round 4
// baseline (speedup 1.0000x reference)
#include <cuda_runtime.h>
#include <math.h>

#define TSEQ   1024
#define NBATCH 64
#define HID    512
#define G3     1536
#define INFEAT 256
#define MROWS  (TSEQ * NBATCH)   // 65536
#define NCTA   128

// packed f32x2 FMA
#define FMA2(d, a, b, c) \
    asm("fma.rn.f32x2 %0, %1, %2, %3;" : "=l"(d) : "l"(a), "l"(b), "l"(c))

__device__ __forceinline__ float2 u2f2(unsigned long long u) {
    float2 f;
    asm("mov.b64 {%0, %1}, %2;" : "=f"(f.x), "=f"(f.y) : "l"(u));
    return f;
}

// ---------------- scratch (device globals; no allocation) ----------------
__device__ float g_xg[(size_t)MROWS * G3];   // [t*64+b][1536] gate preacts
__device__ float g_y0[(size_t)MROWS * HID];  // [t*64+b][512]  tanh(h) of layer 0
__device__ float g_h[2][HID * NBATCH];       // k-major: [buf][k][b]
__device__ unsigned g_slot[NCTA * 32];       // per-CTA arrival slot, 128B stride
__device__ unsigned g_gen2;                  // global generation (monotonic)

// ---------------- input projection GEMM: g_xg = A @ W + bias ----------------
__global__ void __launch_bounds__(256) proj_kernel(
    const float* __restrict__ Aext, const float* __restrict__ W,
    const float* __restrict__ bias,
    int K, long sB, long sT)
{
    const int N = G3;
    const float* A = Aext ? Aext : g_y0;

    __shared__ __align__(16) float As2[16][260];  // duplicated pairs: [k][2*row]
    __shared__ __align__(16) float Bs[16][64];    // [k][col]

    int tid  = threadIdx.x;
    int row0 = blockIdx.y * 128;
    int col0 = blockIdx.x * 64;
    int tx = tid & 15, ty = tid >> 4;

    int ar  = row0 + (tid >> 1);
    const float* arow = A + (long)(ar & 63) * sB + (long)(ar >> 6) * sT;
    int akc = (tid & 1) * 8;
    int r2  = (tid >> 1) * 2;

    int bkr = tid >> 4;
    int bc  = (tid & 15) * 4;
    const float* bptr = W + (long)bkr * N + col0 + bc;

    unsigned long long acc[8][2];
#pragma unroll
    for (int i = 0; i < 8; ++i) { acc[i][0] = 0ull; acc[i][1] = 0ull; }

    for (int k0 = 0; k0 < K; k0 += 16) {
        float4 a0 = *(const float4*)(arow + k0 + akc);
        float4 a1 = *(const float4*)(arow + k0 + akc + 4);
        float4 bb = *(const float4*)(bptr + (long)k0 * N);

        *(float2*)&As2[akc + 0][r2] = make_float2(a0.x, a0.x);
        *(float2*)&As2[akc + 1][r2] = make_float2(a0.y, a0.y);
        *(float2*)&As2[akc + 2][r2] = make_float2(a0.z, a0.z);
        *(float2*)&As2[akc + 3][r2] = make_float2(a0.w, a0.w);
        *(float2*)&As2[akc + 4][r2] = make_float2(a1.x, a1.x);
        *(float2*)&As2[akc + 5][r2] = make_float2(a1.y, a1.y);
        *(float2*)&As2[akc + 6][r2] = make_float2(a1.z, a1.z);
        *(float2*)&As2[akc + 7][r2] = make_float2(a1.w, a1.w);
        *(float4*)&Bs[bkr][bc] = bb;
        __syncthreads();

#pragma unroll
        for (int kk = 0; kk < 16; ++kk) {
            ulonglong2 b01 = *(const ulonglong2*)&Bs[kk][tx * 4];
            ulonglong2 a01 = *(const ulonglong2*)&As2[kk][ty * 16];
            ulonglong2 a23 = *(const ulonglong2*)&As2[kk][ty * 16 + 4];
            ulonglong2 a45 = *(const ulonglong2*)&As2[kk][ty * 16 + 8];
            ulonglong2 a67 = *(const ulonglong2*)&As2[kk][ty * 16 + 12];
            unsigned long long ad[8] = {a01.x, a01.y, a23.x, a23.y,
                                        a45.x, a45.y, a67.x, a67.y};
#pragma unroll
            for (int i = 0; i < 8; ++i) {
                FMA2(acc[i][0], ad[i], b01.x, acc[i][0]);
                FMA2(acc[i][1], ad[i], b01.y, acc[i][1]);
            }
        }
        __syncthreads();
    }

    float4 bia = *(const float4*)(bias + col0 + tx * 4);
#pragma unroll
    for (int i = 0; i < 8; ++i) {
        long m = row0 + ty * 8 + i;
        float2 f01 = u2f2(acc[i][0]);
        float2 f23 = u2f2(acc[i][1]);
        float4 v;
        v.x = f01.x + bia.x;
        v.y = f01.y + bia.y;
        v.z = f23.x + bia.z;
        v.w = f23.y + bia.w;
        *(float4*)(g_xg + m * G3 + col0 + tx * 4) = v;
    }
}

// ---------------- persistent GRU recurrence ----------------
// 128 CTAs x 256 threads. CTA (bgrp, hcgrp): batch rows [bgrp*32,+32),
// hidden cols [hcgrp*8,+8). Distributed-slot grid barrier (no atomics).
__global__ void __launch_bounds__(256, 1) gru_rec_kernel(
    const float* __restrict__ Wh, const float* __restrict__ bhn,
    int write_y, float* __restrict__ cout)
{
    const int NB = 32, NG = 24;
    extern __shared__ __align__(16) float sh[];
    float* ws  = sh;                 // [512][24]
    float* hs  = ws + 512 * NG;      // [512][36]
    float* red = hs + 512 * 36;      // [8][32][26]
    float* xgs = red + 8 * 32 * 26;  // [32][25]

    int tid  = threadIdx.x;
    int warp = tid >> 5, lane = tid & 31;
    int cta  = blockIdx.x;
    int bgrp = cta & 1;
    int hc0  = (cta >> 1) * 8;
    int b0   = bgrp * NB;

    // load W_h slice into SMEM (once)
    for (int f = tid; f < 512 * NG; f += 256) {
        int k = f / NG, j = f - k * NG;
        int gc = (j >> 3) * HID + hc0 + (j & 7);
        ws[f] = Wh[(long)k * G3 + gc];
    }

    unsigned base = *((volatile unsigned*)&g_gen2);   // stable pre-launch value

    int eci = tid & 7;
    int eb  = tid >> 3;
    int ehc = hc0 + eci;
    float bhn_r = bhn[ehc];                           // hoisted, constant over t

    // xg prefetch registers (warps 0-2: grp = warp, b = lane)
    float4 xv0, xv1;
    const float* xg_base = 0;
    if (tid < 96) {
        int b = tid & 31, grp = tid >> 5;
        xg_base = g_xg + (long)(b0 + b) * G3 + grp * HID + hc0;
        const float* p = xg_base;                     // t = 0
        xv0 = ((const float4*)p)[0];
        xv1 = ((const float4*)p)[1];
    }

    for (int t = 0; t < TSEQ; ++t) {
        int cur = t & 1, nxt = cur ^ 1;

        // store prefetched xg tile [32 b][24 gate cols]
        if (tid < 96) {
            int b = tid & 31, grp = tid >> 5;
            float* q = xgs + b * 25 + grp * 8;
            q[0] = xv0.x; q[1] = xv0.y; q[2] = xv0.z; q[3] = xv0.w;
            q[4] = xv1.x; q[5] = xv1.y; q[6] = xv1.z; q[7] = xv1.w;
        }

        // stage h (k-major global -> SMEM [k][36]); t==0: zeros
        if (t == 0) {
            for (int f = tid; f < 512 * 36; f += 256) hs[f] = 0.f;
        } else {
#pragma unroll
            for (int it = 0; it < 16; ++it) {
                int f4 = tid + it * 256;
                int k = f4 >> 3, bq = f4 & 7;
                float4 v = __ldcg((const float4*)&g_h[cur][k * NBATCH + b0 + bq * 4]);
                *(float4*)(hs + k * 36 + bq * 4) = v;
            }
        }
        __syncthreads();

        // partial GEMM: warp w covers k in [w*64, w*64+64)
        unsigned long long acc[12];
#pragma unroll
        for (int j = 0; j < 12; ++j) acc[j] = 0ull;
        int kbase = warp << 6;
#pragma unroll 4
        for (int kk = 0; kk < 64; ++kk) {
            int k = kbase + kk;
            float hv = hs[k * 36 + lane];
            unsigned long long hd;
            asm("mov.b64 %0, {%1, %1};" : "=l"(hd) : "r"(__float_as_int(hv)));
            const ulonglong2* wp = (const ulonglong2*)(ws + k * NG);
            ulonglong2 w0 = wp[0], w1 = wp[1], w2 = wp[2];
            FMA2(acc[0],  hd, w0.x, acc[0]);
            FMA2(acc[1],  hd, w0.y, acc[1]);
            FMA2(acc[2],  hd, w1.x, acc[2]);
            FMA2(acc[3],  hd, w1.y, acc[3]);
            FMA2(acc[4],  hd, w2.x, acc[4]);
            FMA2(acc[5],  hd, w2.y, acc[5]);
            ulonglong2 w3 = wp[3], w4 = wp[4], w5 = wp[5];
            FMA2(acc[6],  hd, w3.x, acc[6]);
            FMA2(acc[7],  hd, w3.y, acc[7]);
            FMA2(acc[8],  hd, w4.x, acc[8]);
            FMA2(acc[9],  hd, w4.y, acc[9]);
            FMA2(acc[10], hd, w5.x, acc[10]);
            FMA2(acc[11], hd, w5.y, acc[11]);
        }
        {
            unsigned long long* rp =
                (unsigned long long*)(red + (warp * NB + lane) * 26);
#pragma unroll
            for (int j = 0; j < 12; ++j) rp[j] = acc[j];
        }
        __syncthreads();

        // reduce 8 warps + gate math
        float hr = 0.f, hz = 0.f, hnv = 0.f;
#pragma unroll
        for (int w = 0; w < 8; ++w) {
            const float* pr = red + (w * NB + eb) * 26;
            hr  += pr[eci];
            hz  += pr[8 + eci];
            hnv += pr[16 + eci];
        }
        float xr = xgs[eb * 25 + eci];
        float xz = xgs[eb * 25 + 8 + eci];
        float xn = xgs[eb * 25 + 16 + eci];
        float hprev = hs[ehc * 36 + eb];

        float rg = 1.f / (1.f + __expf(-(xr + hr)));
        float zg = 1.f / (1.f + __expf(-(xz + hz)));
        float ng = tanhf(xn + rg * (hnv + bhn_r));
        float hnew = (1.f - zg) * ng + zg * hprev;

        g_h[nxt][ehc * NBATCH + b0 + eb] = hnew;
        if (write_y)
            g_y0[((long)t * NBATCH + b0 + eb) * HID + ehc] = tanhf(hnew);
        if (t == TSEQ - 1)
            cout[(b0 + eb) * HID + ehc] = hnew;

        __syncthreads();   // all CTA writes done (block-scope observed)

        unsigned target = base + (unsigned)t + 1u;

        // arrive: one release store to this CTA's private slot (no atomics)
        if (tid == 0)
            asm volatile("st.release.gpu.global.u32 [%0], %1;"
                         :: "l"(&g_slot[cta * 32]), "r"(target) : "memory");

        // overlap: prefetch xg for t+1 while the barrier completes
        if (tid < 96 && t + 1 < TSEQ) {
            const float* p = xg_base + (long)(t + 1) * NBATCH * G3;
            xv0 = ((const float4*)p)[0];
            xv1 = ((const float4*)p)[1];
        }

        // leader (CTA 0, warp 0): gather all 128 slots, then publish gen
        if (cta == 0 && tid < 32) {
            unsigned ok;
            do {
                ok = 1u;
#pragma unroll
                for (int j = 0; j < 4; ++j) {
                    unsigned v;
                    asm volatile("ld.acquire.gpu.global.u32 %0, [%1];"
                                 : "=r"(v) : "l"(&g_slot[(tid * 4 + j) * 32]));
                    if ((int)(v - target) < 0) ok = 0u;
                }
            } while (!__all_sync(0xFFFFFFFFu, ok));
            if (tid == 0)
                asm volatile("st.release.gpu.global.u32 [%0], %1;"
                             :: "l"(&g_gen2), "r"(target) : "memory");
        }

        // everyone: tid0 waits for gen, then block barrier fans out
        if (tid == 0) {
            unsigned v;
            do {
                asm volatile("ld.acquire.gpu.global.u32 %0, [%1];"
                             : "=r"(v) : "l"(&g_gen2));
            } while ((int)(v - target) < 0);
        }
        __syncthreads();
    }
}

// ---------------- dense head: out = tanh(tanh(c1) @ W_out + b_out) ----------------
__global__ void __launch_bounds__(512) dense_kernel(
    const float* __restrict__ Wout, const float* __restrict__ bout,
    float* __restrict__ out)
{
    __shared__ float tsh[HID];
    int b = blockIdx.x;
    int j = threadIdx.x;
    tsh[j] = tanhf(g_h[0][j * NBATCH + b]);   // final h of layer 1 (k-major)
    __syncthreads();
    float s = bout[j];
#pragma unroll 8
    for (int k = 0; k < HID; ++k)
        s = fmaf(tsh[k], Wout[(long)k * 512 + j], s);
    out[b * 512 + j] = tanhf(s);
}

// ---------------- launch ----------------
extern "C" void kernel_launch(void* const* d_in, const int* in_sizes, int n_in,
                              void* d_out, int out_size)
{
    const float* x     = (const float*)d_in[0];
    const float* W_i0  = (const float*)d_in[1];
    const float* b_i0  = (const float*)d_in[2];
    const float* W_h0  = (const float*)d_in[3];
    const float* b_hn0 = (const float*)d_in[4];
    const float* W_i1  = (const float*)d_in[5];
    const float* b_i1  = (const float*)d_in[6];
    const float* W_h1  = (const float*)d_in[7];
    const float* b_hn1 = (const float*)d_in[8];
    const float* W_out = (const float*)d_in[9];
    const float* b_out = (const float*)d_in[10];

    float* out = (float*)d_out;
    float* c0  = out + 64 * 512;
    float* c1  = out + 2 * 64 * 512;

    size_t rec_smem = (size_t)(512 * 24 + 512 * 36 + 8 * 32 * 26 + 32 * 25) * sizeof(float);
    cudaFuncSetAttribute(gru_rec_kernel,
                         cudaFuncAttributeMaxDynamicSharedMemorySize, (int)rec_smem);

    dim3 pgrid(G3 / 64, MROWS / 128);

    // layer 0
    proj_kernel<<<pgrid, 256>>>(x, W_i0, b_i0, INFEAT, (long)1024 * 256, (long)256);
    gru_rec_kernel<<<NCTA, 256, rec_smem>>>(W_h0, b_hn0, 1, c0);
    // layer 1
    proj_kernel<<<pgrid, 256>>>(nullptr, W_i1, b_i1, HID, (long)512, (long)64 * 512);
    gru_rec_kernel<<<NCTA, 256, rec_smem>>>(W_h1, b_hn1, 0, c1);
    // head
    dense_kernel<<<64, 512>>>(W_out, b_out, out);
}

// round 5
// speedup vs baseline: 1.0912x; 1.0912x over previous
#include <cuda_runtime.h>
#include <math.h>

#define TSEQ   1024
#define NBATCH 64
#define HID    512
#define G3     1536
#define INFEAT 256
#define MROWS  (TSEQ * NBATCH)   // 65536
#define NCTA   128

// packed f32x2 FMA
#define FMA2(d, a, b, c) \
    asm("fma.rn.f32x2 %0, %1, %2, %3;" : "=l"(d) : "l"(a), "l"(b), "l"(c))

__device__ __forceinline__ float2 u2f2(unsigned long long u) {
    float2 f;
    asm("mov.b64 {%0, %1}, %2;" : "=f"(f.x), "=f"(f.y) : "l"(u));
    return f;
}

// ---------------- scratch (device globals; no allocation) ----------------
__device__ float g_xg[(size_t)MROWS * G3];   // [t*64+b][1536] gate preacts
__device__ float g_y0[(size_t)MROWS * HID];  // [t*64+b][512]  tanh(h) of layer 0
__device__ float g_h[2][HID * NBATCH];       // k-major: [buf][k][b]
__device__ unsigned g_slot[NCTA * 32];       // per-CTA arrival slot, 128B stride

// ---------------- input projection GEMM: g_xg = A @ W + bias ----------------
__global__ void __launch_bounds__(256) proj_kernel(
    const float* __restrict__ Aext, const float* __restrict__ W,
    const float* __restrict__ bias,
    int K, long sB, long sT)
{
    const int N = G3;
    const float* A = Aext ? Aext : g_y0;

    __shared__ __align__(16) float As2[16][260];  // duplicated pairs: [k][2*row]
    __shared__ __align__(16) float Bs[16][64];    // [k][col]

    int tid  = threadIdx.x;
    int row0 = blockIdx.y * 128;
    int col0 = blockIdx.x * 64;
    int tx = tid & 15, ty = tid >> 4;

    int ar  = row0 + (tid >> 1);
    const float* arow = A + (long)(ar & 63) * sB + (long)(ar >> 6) * sT;
    int akc = (tid & 1) * 8;
    int r2  = (tid >> 1) * 2;

    int bkr = tid >> 4;
    int bc  = (tid & 15) * 4;
    const float* bptr = W + (long)bkr * N + col0 + bc;

    unsigned long long acc[8][2];
#pragma unroll
    for (int i = 0; i < 8; ++i) { acc[i][0] = 0ull; acc[i][1] = 0ull; }

    for (int k0 = 0; k0 < K; k0 += 16) {
        float4 a0 = *(const float4*)(arow + k0 + akc);
        float4 a1 = *(const float4*)(arow + k0 + akc + 4);
        float4 bb = *(const float4*)(bptr + (long)k0 * N);

        *(float2*)&As2[akc + 0][r2] = make_float2(a0.x, a0.x);
        *(float2*)&As2[akc + 1][r2] = make_float2(a0.y, a0.y);
        *(float2*)&As2[akc + 2][r2] = make_float2(a0.z, a0.z);
        *(float2*)&As2[akc + 3][r2] = make_float2(a0.w, a0.w);
        *(float2*)&As2[akc + 4][r2] = make_float2(a1.x, a1.x);
        *(float2*)&As2[akc + 5][r2] = make_float2(a1.y, a1.y);
        *(float2*)&As2[akc + 6][r2] = make_float2(a1.z, a1.z);
        *(float2*)&As2[akc + 7][r2] = make_float2(a1.w, a1.w);
        *(float4*)&Bs[bkr][bc] = bb;
        __syncthreads();

#pragma unroll
        for (int kk = 0; kk < 16; ++kk) {
            ulonglong2 b01 = *(const ulonglong2*)&Bs[kk][tx * 4];
            ulonglong2 a01 = *(const ulonglong2*)&As2[kk][ty * 16];
            ulonglong2 a23 = *(const ulonglong2*)&As2[kk][ty * 16 + 4];
            ulonglong2 a45 = *(const ulonglong2*)&As2[kk][ty * 16 + 8];
            ulonglong2 a67 = *(const ulonglong2*)&As2[kk][ty * 16 + 12];
            unsigned long long ad[8] = {a01.x, a01.y, a23.x, a23.y,
                                        a45.x, a45.y, a67.x, a67.y};
#pragma unroll
            for (int i = 0; i < 8; ++i) {
                FMA2(acc[i][0], ad[i], b01.x, acc[i][0]);
                FMA2(acc[i][1], ad[i], b01.y, acc[i][1]);
            }
        }
        __syncthreads();
    }

    float4 bia = *(const float4*)(bias + col0 + tx * 4);
#pragma unroll
    for (int i = 0; i < 8; ++i) {
        long m = row0 + ty * 8 + i;
        float2 f01 = u2f2(acc[i][0]);
        float2 f23 = u2f2(acc[i][1]);
        float4 v;
        v.x = f01.x + bia.x;
        v.y = f01.y + bia.y;
        v.z = f23.x + bia.z;
        v.w = f23.y + bia.w;
        *(float4*)(g_xg + m * G3 + col0 + tx * 4) = v;
    }
}

// ---------------- persistent GRU recurrence ----------------
// 128 CTAs x 256 threads. CTA (bgrp, hcgrp): batch rows [bgrp*32,+32),
// hidden cols [hcgrp*8,+8). One-hop all-poll grid barrier (no atomics,
// no leader): every CTA's warp 0 polls all 128 arrival slots itself.
__global__ void __launch_bounds__(256, 1) gru_rec_kernel(
    const float* __restrict__ Wh, const float* __restrict__ bhn,
    int write_y, float* __restrict__ cout)
{
    const int NB = 32, NG = 24;
    extern __shared__ __align__(16) float sh[];
    float* ws  = sh;                 // [512][24]
    float* hs  = ws + 512 * NG;      // [512][36]
    float* red = hs + 512 * 36;      // [8][32][26]
    float* xgs = red + 8 * 32 * 26;  // [32][25]

    int tid  = threadIdx.x;
    int warp = tid >> 5, lane = tid & 31;
    int cta  = blockIdx.x;
    int bgrp = cta & 1;
    int hc0  = (cta >> 1) * 8;
    int b0   = bgrp * NB;

    // load W_h slice into SMEM (once)
    for (int f = tid; f < 512 * NG; f += 256) {
        int k = f / NG, j = f - k * NG;
        int gc = (j >> 3) * HID + hc0 + (j & 7);
        ws[f] = Wh[(long)k * G3 + gc];
    }

    // base generation: all slots are uniform at launch boundaries
    unsigned base = *((volatile unsigned*)&g_slot[cta * 32]);

    int eci = tid & 7;
    int eb  = tid >> 3;
    int ehc = hc0 + eci;
    float bhn_r = bhn[ehc];

    // xg prefetch registers (warps 0-2: grp = warp, b = lane)
    float4 xv0, xv1;
    const float* xg_base = 0;
    if (tid < 96) {
        int b = tid & 31, grp = tid >> 5;
        xg_base = g_xg + (long)(b0 + b) * G3 + grp * HID + hc0;
        const float* p = xg_base;                     // t = 0
        xv0 = ((const float4*)p)[0];
        xv1 = ((const float4*)p)[1];
    }

    for (int t = 0; t < TSEQ; ++t) {
        int cur = t & 1, nxt = cur ^ 1;

        // store prefetched xg tile [32 b][24 gate cols]
        if (tid < 96) {
            int b = tid & 31, grp = tid >> 5;
            float* q = xgs + b * 25 + grp * 8;
            q[0] = xv0.x; q[1] = xv0.y; q[2] = xv0.z; q[3] = xv0.w;
            q[4] = xv1.x; q[5] = xv1.y; q[6] = xv1.z; q[7] = xv1.w;
        }

        // stage h (k-major global -> SMEM [k][36]); t==0: zeros
        if (t == 0) {
            for (int f = tid; f < 512 * 36; f += 256) hs[f] = 0.f;
        } else {
#pragma unroll
            for (int it = 0; it < 16; ++it) {
                int f4 = tid + it * 256;
                int k = f4 >> 3, bq = f4 & 7;
                float4 v = __ldcg((const float4*)&g_h[cur][k * NBATCH + b0 + bq * 4]);
                *(float4*)(hs + k * 36 + bq * 4) = v;
            }
        }
        __syncthreads();

        // partial GEMM: warp w covers k in [w*64, w*64+64)
        unsigned long long acc[12];
#pragma unroll
        for (int j = 0; j < 12; ++j) acc[j] = 0ull;
        int kbase = warp << 6;
#pragma unroll 4
        for (int kk = 0; kk < 64; ++kk) {
            int k = kbase + kk;
            float hv = hs[k * 36 + lane];
            unsigned long long hd;
            asm("mov.b64 %0, {%1, %1};" : "=l"(hd) : "r"(__float_as_int(hv)));
            const ulonglong2* wp = (const ulonglong2*)(ws + k * NG);
            ulonglong2 w0 = wp[0], w1 = wp[1], w2 = wp[2];
            FMA2(acc[0],  hd, w0.x, acc[0]);
            FMA2(acc[1],  hd, w0.y, acc[1]);
            FMA2(acc[2],  hd, w1.x, acc[2]);
            FMA2(acc[3],  hd, w1.y, acc[3]);
            FMA2(acc[4],  hd, w2.x, acc[4]);
            FMA2(acc[5],  hd, w2.y, acc[5]);
            ulonglong2 w3 = wp[3], w4 = wp[4], w5 = wp[5];
            FMA2(acc[6],  hd, w3.x, acc[6]);
            FMA2(acc[7],  hd, w3.y, acc[7]);
            FMA2(acc[8],  hd, w4.x, acc[8]);
            FMA2(acc[9],  hd, w4.y, acc[9]);
            FMA2(acc[10], hd, w5.x, acc[10]);
            FMA2(acc[11], hd, w5.y, acc[11]);
        }
        {
            unsigned long long* rp =
                (unsigned long long*)(red + (warp * NB + lane) * 26);
#pragma unroll
            for (int j = 0; j < 12; ++j) rp[j] = acc[j];
        }
        __syncthreads();

        // reduce 8 warps + gate math
        float hr = 0.f, hz = 0.f, hnv = 0.f;
#pragma unroll
        for (int w = 0; w < 8; ++w) {
            const float* pr = red + (w * NB + eb) * 26;
            hr  += pr[eci];
            hz  += pr[8 + eci];
            hnv += pr[16 + eci];
        }
        float xr = xgs[eb * 25 + eci];
        float xz = xgs[eb * 25 + 8 + eci];
        float xn = xgs[eb * 25 + 16 + eci];
        float hprev = hs[ehc * 36 + eb];

        float rg = 1.f / (1.f + __expf(-(xr + hr)));
        float zg = 1.f / (1.f + __expf(-(xz + hz)));
        float ng = tanhf(xn + rg * (hnv + bhn_r));
        float hnew = (1.f - zg) * ng + zg * hprev;

        g_h[nxt][ehc * NBATCH + b0 + eb] = hnew;
        if (write_y)
            g_y0[((long)t * NBATCH + b0 + eb) * HID + ehc] = tanhf(hnew);
        if (t == TSEQ - 1)
            cout[(b0 + eb) * HID + ehc] = hnew;

        __syncthreads();   // all CTA writes issued (block-scope ordering)

        unsigned target = base + (unsigned)t + 1u;

        // arrive: one release store to this CTA's private slot
        if (tid == 0)
            asm volatile("st.release.gpu.global.u32 [%0], %1;"
                         :: "l"(&g_slot[cta * 32]), "r"(target) : "memory");

        // overlap: prefetch xg for t+1 while the barrier completes
        if (tid < 96 && t + 1 < TSEQ) {
            const float* p = xg_base + (long)(t + 1) * NBATCH * G3;
            xv0 = ((const float4*)p)[0];
            xv1 = ((const float4*)p)[1];
        }

        // detect: warp 0 of EVERY CTA polls all 128 slots (one hop)
        if (tid < 32) {
            unsigned ok;
            do {
                ok = 1u;
#pragma unroll
                for (int j = 0; j < 4; ++j) {
                    unsigned v;
                    asm volatile("ld.acquire.gpu.global.u32 %0, [%1];"
                                 : "=r"(v) : "l"(&g_slot[(lane * 4 + j) * 32]));
                    if ((int)(v - target) < 0) ok = 0u;
                }
            } while (!__all_sync(0xFFFFFFFFu, ok));
        }
        __syncthreads();
    }
}

// ---------------- dense head: out = tanh(tanh(c1) @ W_out + b_out) ----------------
__global__ void __launch_bounds__(512) dense_kernel(
    const float* __restrict__ Wout, const float* __restrict__ bout,
    float* __restrict__ out)
{
    __shared__ float tsh[HID];
    int b = blockIdx.x;
    int j = threadIdx.x;
    tsh[j] = tanhf(g_h[0][j * NBATCH + b]);   // final h of layer 1 (k-major)
    __syncthreads();
    float s = bout[j];
#pragma unroll 8
    for (int k = 0; k < HID; ++k)
        s = fmaf(tsh[k], Wout[(long)k * 512 + j], s);
    out[b * 512 + j] = tanhf(s);
}

// ---------------- launch ----------------
extern "C" void kernel_launch(void* const* d_in, const int* in_sizes, int n_in,
                              void* d_out, int out_size)
{
    const float* x     = (const float*)d_in[0];
    const float* W_i0  = (const float*)d_in[1];
    const float* b_i0  = (const float*)d_in[2];
    const float* W_h0  = (const float*)d_in[3];
    const float* b_hn0 = (const float*)d_in[4];
    const float* W_i1  = (const float*)d_in[5];
    const float* b_i1  = (const float*)d_in[6];
    const float* W_h1  = (const float*)d_in[7];
    const float* b_hn1 = (const float*)d_in[8];
    const float* W_out = (const float*)d_in[9];
    const float* b_out = (const float*)d_in[10];

    float* out = (float*)d_out;
    float* c0  = out + 64 * 512;
    float* c1  = out + 2 * 64 * 512;

    size_t rec_smem = (size_t)(512 * 24 + 512 * 36 + 8 * 32 * 26 + 32 * 25) * sizeof(float);
    cudaFuncSetAttribute(gru_rec_kernel,
                         cudaFuncAttributeMaxDynamicSharedMemorySize, (int)rec_smem);

    dim3 pgrid(G3 / 64, MROWS / 128);

    // layer 0
    proj_kernel<<<pgrid, 256>>>(x, W_i0, b_i0, INFEAT, (long)1024 * 256, (long)256);
    gru_rec_kernel<<<NCTA, 256, rec_smem>>>(W_h0, b_hn0, 1, c0);
    // layer 1
    proj_kernel<<<pgrid, 256>>>(nullptr, W_i1, b_i1, HID, (long)512, (long)64 * 512);
    gru_rec_kernel<<<NCTA, 256, rec_smem>>>(W_h1, b_hn1, 0, c1);
    // head
    dense_kernel<<<64, 512>>>(W_out, b_out, out);
}

// round 8
// speedup vs baseline: 1.3258x; 1.2150x over previous
#include <cuda_runtime.h>
#include <math.h>

#define TSEQ   1024
#define NBATCH 64
#define HID    512
#define G3     1536
#define INFEAT 256
#define MROWS  (TSEQ * NBATCH)   // 65536
#define NCTA   128

// packed f32x2 FMA
#define FMA2(d, a, b, c) \
    asm("fma.rn.f32x2 %0, %1, %2, %3;" : "=l"(d) : "l"(a), "l"(b), "l"(c))

__device__ __forceinline__ float2 u2f2(unsigned long long u) {
    float2 f;
    asm("mov.b64 {%0, %1}, %2;" : "=f"(f.x), "=f"(f.y) : "l"(u));
    return f;
}

// ---------------- scratch (device globals; no allocation) ----------------
__device__ float g_xg[(size_t)MROWS * G3];   // [t*64+b][1536] gate preacts
__device__ float g_y0[(size_t)MROWS * HID];  // [t*64+b][512]  tanh(h) of layer 0
__device__ float g_h[3][HID * NBATCH];       // k-major [buf][k][b]; buf2 = zero
__device__ unsigned g_cnt;                   // barrier count (returns to 0)
__device__ unsigned g_gen;                   // generation (monotonic)

// ---------------- input projection GEMM: g_xg = A @ W + bias ----------------
__global__ void __launch_bounds__(256) proj_kernel(
    const float* __restrict__ Aext, const float* __restrict__ W,
    const float* __restrict__ bias,
    int K, long sB, long sT)
{
    const int N = G3;
    const float* A = Aext ? Aext : g_y0;

    __shared__ __align__(16) float As2[16][260];  // duplicated pairs: [k][2*row]
    __shared__ __align__(16) float Bs[16][64];    // [k][col]

    int tid  = threadIdx.x;
    int row0 = blockIdx.y * 128;
    int col0 = blockIdx.x * 64;
    int tx = tid & 15, ty = tid >> 4;

    int ar  = row0 + (tid >> 1);
    const float* arow = A + (long)(ar & 63) * sB + (long)(ar >> 6) * sT;
    int akc = (tid & 1) * 8;
    int r2  = (tid >> 1) * 2;

    int bkr = tid >> 4;
    int bc  = (tid & 15) * 4;
    const float* bptr = W + (long)bkr * N + col0 + bc;

    unsigned long long acc[8][2];
#pragma unroll
    for (int i = 0; i < 8; ++i) { acc[i][0] = 0ull; acc[i][1] = 0ull; }

    for (int k0 = 0; k0 < K; k0 += 16) {
        float4 a0 = *(const float4*)(arow + k0 + akc);
        float4 a1 = *(const float4*)(arow + k0 + akc + 4);
        float4 bb = *(const float4*)(bptr + (long)k0 * N);

        *(float2*)&As2[akc + 0][r2] = make_float2(a0.x, a0.x);
        *(float2*)&As2[akc + 1][r2] = make_float2(a0.y, a0.y);
        *(float2*)&As2[akc + 2][r2] = make_float2(a0.z, a0.z);
        *(float2*)&As2[akc + 3][r2] = make_float2(a0.w, a0.w);
        *(float2*)&As2[akc + 4][r2] = make_float2(a1.x, a1.x);
        *(float2*)&As2[akc + 5][r2] = make_float2(a1.y, a1.y);
        *(float2*)&As2[akc + 6][r2] = make_float2(a1.z, a1.z);
        *(float2*)&As2[akc + 7][r2] = make_float2(a1.w, a1.w);
        *(float4*)&Bs[bkr][bc] = bb;
        __syncthreads();

#pragma unroll
        for (int kk = 0; kk < 16; ++kk) {
            ulonglong2 b01 = *(const ulonglong2*)&Bs[kk][tx * 4];
            ulonglong2 a01 = *(const ulonglong2*)&As2[kk][ty * 16];
            ulonglong2 a23 = *(const ulonglong2*)&As2[kk][ty * 16 + 4];
            ulonglong2 a45 = *(const ulonglong2*)&As2[kk][ty * 16 + 8];
            ulonglong2 a67 = *(const ulonglong2*)&As2[kk][ty * 16 + 12];
            unsigned long long ad[8] = {a01.x, a01.y, a23.x, a23.y,
                                        a45.x, a45.y, a67.x, a67.y};
#pragma unroll
            for (int i = 0; i < 8; ++i) {
                FMA2(acc[i][0], ad[i], b01.x, acc[i][0]);
                FMA2(acc[i][1], ad[i], b01.y, acc[i][1]);
            }
        }
        __syncthreads();
    }

    float4 bia = *(const float4*)(bias + col0 + tx * 4);
#pragma unroll
    for (int i = 0; i < 8; ++i) {
        long m = row0 + ty * 8 + i;
        float2 f01 = u2f2(acc[i][0]);
        float2 f23 = u2f2(acc[i][1]);
        float4 v;
        v.x = f01.x + bia.x;
        v.y = f01.y + bia.y;
        v.z = f23.x + bia.z;
        v.w = f23.y + bia.w;
        *(float4*)(g_xg + m * G3 + col0 + tx * 4) = v;
    }
}

// ---------------- persistent GRU recurrence ----------------
// 128 CTAs x 256 threads. CTA (bgrp, hcgrp): batch rows [bgrp*32,+32),
// hidden cols [hcgrp*8,+8). h read straight from L2 in the GEMM loop
// (no SMEM staging burst). Central count+gen barrier, release/acquire.
__global__ void __launch_bounds__(256, 1) gru_rec_kernel(
    const float* __restrict__ Wh, const float* __restrict__ bhn,
    int write_y, float* __restrict__ cout)
{
    const int NB = 32, NG = 24;
    extern __shared__ __align__(16) float sh[];
    float* ws  = sh;                 // [512][24]  48 KB
    float* red = ws + 512 * NG;      // [8][32][26] 26 KB
    float* xgs = red + 8 * 32 * 26;  // [32][25]   2.5 KB

    int tid  = threadIdx.x;
    int warp = tid >> 5, lane = tid & 31;
    int cta  = blockIdx.x;
    int bgrp = cta & 1;
    int hc0  = (cta >> 1) * 8;
    int b0   = bgrp * NB;

    // load W_h slice into SMEM (once)
    for (int f = tid; f < 512 * NG; f += 256) {
        int k = f / NG, j = f - k * NG;
        int gc = (j >> 3) * HID + hc0 + (j & 7);
        ws[f] = Wh[(long)k * G3 + gc];
    }

    // gen only advances after ALL CTAs arrive at step-0 barrier -> safe base
    unsigned base = *((volatile unsigned*)&g_gen);

    int eci = tid & 7;
    int eb  = tid >> 3;
    int ehc = hc0 + eci;
    float bhn_r = bhn[ehc];

    // xg prefetch registers (warps 0-2: grp = warp, b = lane)
    float4 xv0, xv1;
    const float* xg_base = 0;
    if (tid < 96) {
        int b = tid & 31, grp = tid >> 5;
        xg_base = g_xg + (long)(b0 + b) * G3 + grp * HID + hc0;
        const float* p = xg_base;                     // t = 0
        xv0 = ((const float4*)p)[0];
        xv1 = ((const float4*)p)[1];
    }

    for (int t = 0; t < TSEQ; ++t) {
        int nxt = (t & 1) ^ 1;
        // t==0 reads the never-written zero buffer (branchless, stale-safe)
        const float* hbuf = (t == 0) ? g_h[2] : g_h[t & 1];

        // early: previous h for the gate update (latency hidden under GEMM)
        float hprev = __ldcg(&hbuf[ehc * NBATCH + b0 + eb]);

        // store prefetched xg tile [32 b][24 gate cols]
        if (tid < 96) {
            int b = tid & 31, grp = tid >> 5;
            float* q = xgs + b * 25 + grp * 8;
            q[0] = xv0.x; q[1] = xv0.y; q[2] = xv0.z; q[3] = xv0.w;
            q[4] = xv1.x; q[5] = xv1.y; q[6] = xv1.z; q[7] = xv1.w;
        }

        // partial GEMM: warp w covers k in [w*64, w*64+64), h straight from L2
        unsigned long long acc[12];
#pragma unroll
        for (int j = 0; j < 12; ++j) acc[j] = 0ull;
        int kbase = warp << 6;
        const float* hp = hbuf + (kbase << 6) + b0 + lane;   // + k*64
        const ulonglong2* wp = (const ulonglong2*)(ws + kbase * NG);
#pragma unroll 8
        for (int kk = 0; kk < 64; ++kk) {
            float hv = __ldcg(hp); hp += NBATCH;
            unsigned long long hd;
            asm("mov.b64 %0, {%1, %1};" : "=l"(hd) : "r"(__float_as_int(hv)));
            ulonglong2 w0 = wp[0], w1 = wp[1], w2 = wp[2];
            FMA2(acc[0],  hd, w0.x, acc[0]);
            FMA2(acc[1],  hd, w0.y, acc[1]);
            FMA2(acc[2],  hd, w1.x, acc[2]);
            FMA2(acc[3],  hd, w1.y, acc[3]);
            FMA2(acc[4],  hd, w2.x, acc[4]);
            FMA2(acc[5],  hd, w2.y, acc[5]);
            ulonglong2 w3 = wp[3], w4 = wp[4], w5 = wp[5];
            FMA2(acc[6],  hd, w3.x, acc[6]);
            FMA2(acc[7],  hd, w3.y, acc[7]);
            FMA2(acc[8],  hd, w4.x, acc[8]);
            FMA2(acc[9],  hd, w4.y, acc[9]);
            FMA2(acc[10], hd, w5.x, acc[10]);
            FMA2(acc[11], hd, w5.y, acc[11]);
            wp += 6;   // row stride = 24 floats = 6 ulonglong2 (R7 bug: was +3)
        }
        {
            unsigned long long* rp =
                (unsigned long long*)(red + (warp * NB + lane) * 26);
#pragma unroll
            for (int j = 0; j < 12; ++j) rp[j] = acc[j];
        }
        __syncthreads();   // red + xgs visible

        // reduce 8 warps + gate math
        float hr = 0.f, hz = 0.f, hnv = 0.f;
#pragma unroll
        for (int w = 0; w < 8; ++w) {
            const float* pr = red + (w * NB + eb) * 26;
            hr  += pr[eci];
            hz  += pr[8 + eci];
            hnv += pr[16 + eci];
        }
        float xr = xgs[eb * 25 + eci];
        float xz = xgs[eb * 25 + 8 + eci];
        float xn = xgs[eb * 25 + 16 + eci];

        float rg = 1.f / (1.f + __expf(-(xr + hr)));
        float zg = 1.f / (1.f + __expf(-(xz + hz)));
        float ng = tanhf(xn + rg * (hnv + bhn_r));
        float hnew = (1.f - zg) * ng + zg * hprev;

        g_h[nxt][ehc * NBATCH + b0 + eb] = hnew;
        if (write_y)
            g_y0[((long)t * NBATCH + b0 + eb) * HID + ehc] = tanhf(hnew);
        if (t == TSEQ - 1)
            cout[(b0 + eb) * HID + ehc] = hnew;

        __syncthreads();   // all CTA writes issued before tid0's release

        unsigned target = base + (unsigned)t + 1u;

        // arrive: release-atomic (publishes the CTA's writes)
        if (tid == 0) {
            unsigned old;
            asm volatile("atom.release.gpu.global.add.u32 %0, [%1], %2;"
                         : "=r"(old) : "l"(&g_cnt), "r"(1u) : "memory");
            if (old == NCTA - 1u) {
                asm volatile("st.global.u32 [%0], %1;"
                             :: "l"(&g_cnt), "r"(0u) : "memory");
                asm volatile("st.release.gpu.global.u32 [%0], %1;"
                             :: "l"(&g_gen), "r"(target) : "memory");
            }
        }

        // overlap: prefetch xg for t+1 while the barrier completes
        if (tid < 96 && t + 1 < TSEQ) {
            const float* p = xg_base + (long)(t + 1) * NBATCH * G3;
            xv0 = ((const float4*)p)[0];
            xv1 = ((const float4*)p)[1];
        }

        // detect: tid0 acquire-polls gen, block barrier fans out
        if (tid == 0) {
            unsigned v;
            do {
                asm volatile("ld.acquire.gpu.global.u32 %0, [%1];"
                             : "=r"(v) : "l"(&g_gen));
            } while ((int)(v - target) < 0);
        }
        __syncthreads();
    }
}

// ---------------- dense head: out = tanh(tanh(c1) @ W_out + b_out) ----------------
__global__ void __launch_bounds__(512) dense_kernel(
    const float* __restrict__ Wout, const float* __restrict__ bout,
    float* __restrict__ out)
{
    __shared__ float tsh[HID];
    int b = blockIdx.x;
    int j = threadIdx.x;
    tsh[j] = tanhf(g_h[0][j * NBATCH + b]);   // final h of layer 1 (k-major)
    __syncthreads();
    float s = bout[j];
#pragma unroll 8
    for (int k = 0; k < HID; ++k)
        s = fmaf(tsh[k], Wout[(long)k * 512 + j], s);
    out[b * 512 + j] = tanhf(s);
}

// ---------------- launch ----------------
extern "C" void kernel_launch(void* const* d_in, const int* in_sizes, int n_in,
                              void* d_out, int out_size)
{
    const float* x     = (const float*)d_in[0];
    const float* W_i0  = (const float*)d_in[1];
    const float* b_i0  = (const float*)d_in[2];
    const float* W_h0  = (const float*)d_in[3];
    const float* b_hn0 = (const float*)d_in[4];
    const float* W_i1  = (const float*)d_in[5];
    const float* b_i1  = (const float*)d_in[6];
    const float* W_h1  = (const float*)d_in[7];
    const float* b_hn1 = (const float*)d_in[8];
    const float* W_out = (const float*)d_in[9];
    const float* b_out = (const float*)d_in[10];

    float* out = (float*)d_out;
    float* c0  = out + 64 * 512;
    float* c1  = out + 2 * 64 * 512;

    size_t rec_smem = (size_t)(512 * 24 + 8 * 32 * 26 + 32 * 25) * sizeof(float);
    cudaFuncSetAttribute(gru_rec_kernel,
                         cudaFuncAttributeMaxDynamicSharedMemorySize, (int)rec_smem);

    dim3 pgrid(G3 / 64, MROWS / 128);

    // layer 0
    proj_kernel<<<pgrid, 256>>>(x, W_i0, b_i0, INFEAT, (long)1024 * 256, (long)256);
    gru_rec_kernel<<<NCTA, 256, rec_smem>>>(W_h0, b_hn0, 1, c0);
    // layer 1
    proj_kernel<<<pgrid, 256>>>(nullptr, W_i1, b_i1, HID, (long)512, (long)64 * 512);
    gru_rec_kernel<<<NCTA, 256, rec_smem>>>(W_h1, b_hn1, 0, c1);
    // head
    dense_kernel<<<64, 512>>>(W_out, b_out, out);
}